// round 1
// baseline (speedup 1.0000x reference)
#include <cuda_runtime.h>
#include <cuda_bf16.h>

// IntervalDistLoss: loss = LW * (term0/2 + term1/3) / num_pixels
//   term0 = sum_r sum_ij w_i w_j |m_i - m_j|,  m = z + 0.5*delta
//   term1 = sum_r sum_i w_i^2 * delta_i
//
// Kernel 1: one CTA of 128 threads per ray. Full N^2 (double-counts pairs,
// which exactly absorbs the /2). Deterministic block reduce -> per-ray partial.
// Kernel 2: deterministic single-block reduce of partials + final scaling.

#define SAMPLES 128
#define LOSS_WEIGHT 0.01f
#define MAX_RAYS 65536

__device__ float g_partials[MAX_RAYS];

__global__ void __launch_bounds__(SAMPLES)
interval_dist_ray_kernel(const float* __restrict__ z_vals,
                         const float* __restrict__ deltas,
                         const float* __restrict__ weights,
                         float* __restrict__ partials)
{
    __shared__ float2 s_mw[SAMPLES];   // (mid, weight) per sample
    __shared__ float s_warp[SAMPLES / 32];

    const int ray = blockIdx.x;
    const int i = threadIdx.x;
    const size_t base = (size_t)ray * SAMPLES + i;

    const float di = deltas[base];
    const float mi = z_vals[base] + 0.5f * di;
    const float wi = weights[base];

    s_mw[i] = make_float2(mi, wi);
    __syncthreads();

    // row i of the pair interaction: acc = sum_j w_j * |m_i - m_j|
    float acc = 0.0f;
#pragma unroll 16
    for (int j = 0; j < SAMPLES; ++j) {
        float2 mw = s_mw[j];                 // LDS.64 broadcast, conflict-free
        acc += mw.y * fabsf(mi - mw.x);      // FADD + FFMA(|.| modifier)
    }

    // per-thread contribution: 0.5 * w_i * row_i  +  (1/3) * w_i^2 * d_i
    float val = 0.5f * wi * acc + (1.0f / 3.0f) * wi * wi * di;

    // deterministic block reduce (shuffle within warp, then 4 partials)
#pragma unroll
    for (int off = 16; off > 0; off >>= 1)
        val += __shfl_down_sync(0xffffffffu, val, off);
    if ((i & 31) == 0) s_warp[i >> 5] = val;
    __syncthreads();
    if (i == 0)
        partials[ray] = (s_warp[0] + s_warp[1]) + (s_warp[2] + s_warp[3]);
}

__global__ void __launch_bounds__(256)
interval_dist_reduce_kernel(const float* __restrict__ partials, int n_rays,
                            const int* __restrict__ num_pixels_ptr,
                            int num_pixels_fallback,
                            float* __restrict__ out)
{
    __shared__ float sdata[256];
    const int tid = threadIdx.x;

    float s = 0.0f;
    for (int r = tid; r < n_rays; r += 256)
        s += partials[r];

    sdata[tid] = s;
    __syncthreads();
#pragma unroll
    for (int stride = 128; stride > 0; stride >>= 1) {
        if (tid < stride) sdata[tid] += sdata[tid + stride];
        __syncthreads();
    }

    if (tid == 0) {
        int np = num_pixels_ptr ? *num_pixels_ptr : num_pixels_fallback;
        out[0] = LOSS_WEIGHT * sdata[0] / (float)np;
    }
}

extern "C" void kernel_launch(void* const* d_in, const int* in_sizes, int n_in,
                              void* d_out, int out_size)
{
    const float* z_vals  = (const float*)d_in[0];
    const float* deltas  = (const float*)d_in[1];
    const float* weights = (const float*)d_in[2];
    const int*   np_ptr  = (n_in >= 4) ? (const int*)d_in[3] : nullptr;

    const int n_rays = in_sizes[0] / SAMPLES;

    float* partials;
    cudaGetSymbolAddress((void**)&partials, g_partials);

    interval_dist_ray_kernel<<<n_rays, SAMPLES>>>(z_vals, deltas, weights, partials);
    interval_dist_reduce_kernel<<<1, 256>>>(partials, n_rays, np_ptr, n_rays,
                                            (float*)d_out);
}